// round 2
// baseline (speedup 1.0000x reference)
#include <cuda_runtime.h>
#include <math.h>

// Problem constants
#define BSZ  64      // batch
#define FDIM 256     // feature (contraction) dim
#define MDIM 128     // M (output tile is MDIM x MDIM)
#define KT   16      // K-tile depth
#define NT   (FDIM / KT)   // 16 k-tiles

// One CTA per (a, b, which) with a <= b (symmetry: hist(a,b) == hist(b,a)).
// 256 threads (16x16), each owns an 8x8 fp32 register tile of the 128x128
// Gram matrix C[m,n] = sum_f mat[a,f,m] * mat[b,f,n].
// Epilogue: block min/max reduce -> torch.histc-style 8-bin histogram
// (floor((x-mn)/(mx-mn)*8), clamp [0,7]) -> L2 normalize -> write both rows.
__global__ __launch_bounds__(256, 2)
void pair_hist_kernel(const float* __restrict__ mat1,
                      const float* __restrict__ mat2,
                      float* __restrict__ out)
{
    const int a = blockIdx.x;
    const int b = blockIdx.y;
    if (b < a) return;                       // uniform exit, no barrier hazard
    const int z = blockIdx.z;                // 0 -> matf1, 1 -> matf2
    const float* __restrict__ mat = (z == 0) ? mat1 : mat2;

    __shared__ float As[KT * MDIM];          // 8 KB
    __shared__ float Bs[KT * MDIM];          // 8 KB
    __shared__ float wmn[8], wmx[8];
    __shared__ float s_mn, s_scale;
    __shared__ unsigned int bins[8];

    const int tid  = threadIdx.x;
    const int tx   = tid & 15;
    const int ty   = tid >> 4;
    const int lane = tid & 31;
    const int wid  = tid >> 5;

    if (tid < 8) bins[tid] = 0u;

    const float* gA = mat + (size_t)a * (FDIM * MDIM);
    const float* gB = mat + (size_t)b * (FDIM * MDIM);

    // ---- GEMM main loop: prefetch-to-registers, single SMEM buffer ----
    float4 ra0, ra1, rb0, rb1;
    {
        const float4* a4 = (const float4*)gA;
        const float4* b4 = (const float4*)gB;
        ra0 = a4[tid];       ra1 = a4[tid + 256];
        rb0 = b4[tid];       rb1 = b4[tid + 256];
    }

    float acc[8][8];
#pragma unroll
    for (int i = 0; i < 8; i++)
#pragma unroll
        for (int j = 0; j < 8; j++) acc[i][j] = 0.0f;

    for (int kt = 0; kt < NT; kt++) {
        float4* As4 = (float4*)As;
        float4* Bs4 = (float4*)Bs;
        As4[tid] = ra0;  As4[tid + 256] = ra1;
        Bs4[tid] = rb0;  Bs4[tid + 256] = rb1;
        __syncthreads();

        if (kt + 1 < NT) {                   // prefetch next tile (LDG overlaps FFMA)
            const float4* a4 = (const float4*)(gA + (kt + 1) * KT * MDIM);
            const float4* b4 = (const float4*)(gB + (kt + 1) * KT * MDIM);
            ra0 = a4[tid];   ra1 = a4[tid + 256];
            rb0 = b4[tid];   rb1 = b4[tid + 256];
        }

#pragma unroll
        for (int kk = 0; kk < KT; kk++) {
            const float4* Ar = (const float4*)(As + kk * MDIM);
            const float4* Br = (const float4*)(Bs + kk * MDIM);
            // rows: m = ty*4+ii and 64+ty*4+ii ; cols: n = tx*4+jj and 64+tx*4+jj
            float4 a0 = Ar[ty], a1 = Ar[ty + 16];
            float4 b0 = Br[tx], b1 = Br[tx + 16];
            float av[8] = {a0.x, a0.y, a0.z, a0.w, a1.x, a1.y, a1.z, a1.w};
            float bv[8] = {b0.x, b0.y, b0.z, b0.w, b1.x, b1.y, b1.z, b1.w};
#pragma unroll
            for (int i = 0; i < 8; i++)
#pragma unroll
                for (int j = 0; j < 8; j++)
                    acc[i][j] = fmaf(av[i], bv[j], acc[i][j]);
        }
        __syncthreads();
    }

    // ---- min/max over the full 128x128 tile (values stay in registers) ----
    float mn = acc[0][0], mx = acc[0][0];
#pragma unroll
    for (int i = 0; i < 8; i++)
#pragma unroll
        for (int j = 0; j < 8; j++) {
            mn = fminf(mn, acc[i][j]);
            mx = fmaxf(mx, acc[i][j]);
        }
#pragma unroll
    for (int o = 16; o > 0; o >>= 1) {
        mn = fminf(mn, __shfl_xor_sync(0xffffffffu, mn, o));
        mx = fmaxf(mx, __shfl_xor_sync(0xffffffffu, mx, o));
    }
    if (lane == 0) { wmn[wid] = mn; wmx[wid] = mx; }
    __syncthreads();
    if (tid == 0) {
        float m0 = wmn[0], M0 = wmx[0];
#pragma unroll
        for (int w = 1; w < 8; w++) {
            m0 = fminf(m0, wmn[w]);
            M0 = fmaxf(M0, wmx[w]);
        }
        float den = (M0 > m0) ? (M0 - m0) : 1.0f;
        s_mn = m0;
        s_scale = 8.0f / den;                // histc: floor((x-mn)/den * 8)
    }
    __syncthreads();

    // ---- per-thread binning into byte-packed counters (no local-mem array) ----
    const float mnv = s_mn, sc = s_scale;
    unsigned int c0 = 0, c1 = 0;             // 8 byte-counters (max 64/bin/thread)
#pragma unroll
    for (int i = 0; i < 8; i++)
#pragma unroll
        for (int j = 0; j < 8; j++) {
            float t = (acc[i][j] - mnv) * sc;
            int idx = (int)floorf(t);
            idx = idx < 0 ? 0 : (idx > 7 ? 7 : idx);
            unsigned int inc = 1u << ((idx & 3) * 8);
            if (idx < 4) c0 += inc; else c1 += inc;
        }
    // warp-reduce each bin, then one shared atomic per warp per bin
#pragma unroll
    for (int bbin = 0; bbin < 8; bbin++) {
        unsigned int v = (bbin < 4) ? ((c0 >> (bbin * 8)) & 0xFFu)
                                    : ((c1 >> ((bbin - 4) * 8)) & 0xFFu);
#pragma unroll
        for (int o = 16; o > 0; o >>= 1)
            v += __shfl_xor_sync(0xffffffffu, v, o);
        if (lane == 0) atomicAdd(&bins[bbin], v);
    }
    __syncthreads();

    // ---- L2 normalize and write both (a,b) and (b,a) rows ----
    if (tid == 0) {
        float h[8], ss = 0.0f;
#pragma unroll
        for (int k = 0; k < 8; k++) { h[k] = (float)bins[k]; ss += h[k] * h[k]; }
        float nrm = fmaxf(sqrtf(ss), 1e-12f);
        const int row1 = (a * BSZ + b) * 16 + z * 8;
        const int row2 = (b * BSZ + a) * 16 + z * 8;
#pragma unroll
        for (int k = 0; k < 8; k++) {
            float v = h[k] / nrm;
            out[row1 + k] = v;
            out[row2 + k] = v;
        }
    }
}

extern "C" void kernel_launch(void* const* d_in, const int* in_sizes, int n_in,
                              void* d_out, int out_size)
{
    const float* m1 = (const float*)d_in[0];   // matf1 [64,256,128] fp32
    const float* m2 = (const float*)d_in[1];   // matf2 [64,256,128] fp32
    float* out = (float*)d_out;                // [4096,16] fp32

    dim3 grid(BSZ, BSZ, 2);
    pair_hist_kernel<<<grid, 256>>>(m1, m2, out);
}

// round 4
// speedup vs baseline: 2.0045x; 2.0045x over previous
#include <cuda_runtime.h>
#include <cuda_bf16.h>
#include <math.h>
#include <stdint.h>

// ---------------- problem constants ----------------
#define BSZ   64
#define FDIM  256
#define MDIM  128
#define KC    64                   // K elements per chunk
#define NCHUNK (FDIM / KC)         // 4
#define PITCH 72                   // bf16 elems per smem row (144 B, 16B-aligned, LDS conflict-free)
#define TBYTES (MDIM * PITCH * 2)  // 18432 B per tile
#define SMEM_DYN (4 * TBYTES)      // Ahi, Alo, Bhi, Blo

// bf16 hi/lo scratch, K-major: [z][batch][m][f]  (8 MB each)
__device__ __nv_bfloat16 g_hi[2u * BSZ * MDIM * FDIM];
__device__ __nv_bfloat16 g_lo[2u * BSZ * MDIM * FDIM];

// ---------------- kernel 1: fp32 -> (hi, lo) bf16 with F<->M transpose ----------------
// in : [bs, F=256, M=128] fp32 ;  out: [z, bs, M=128, F=256] bf16 (K-major)
__global__ void convert_kernel(const float* __restrict__ m1, const float* __restrict__ m2)
{
    __shared__ float tile[32][33];
    const int z = blockIdx.z >> 6;
    const int bat = blockIdx.z & 63;
    const float* __restrict__ src = z ? m2 : m1;
    const int m0 = blockIdx.x * 32;
    const int f0 = blockIdx.y * 32;
    const int tx = threadIdx.x, ty = threadIdx.y;

#pragma unroll
    for (int i = 0; i < 4; i++) {
        int f = f0 + ty + i * 8;
        tile[ty + i * 8][tx] = src[((size_t)bat * FDIM + f) * MDIM + m0 + tx];
    }
    __syncthreads();
#pragma unroll
    for (int i = 0; i < 4; i++) {
        int m = m0 + ty + i * 8;
        int f = f0 + tx;
        float x = tile[tx][ty + i * 8];
        __nv_bfloat16 h = __float2bfloat16(x);
        float r = x - __bfloat162float(h);
        size_t o = (((size_t)(z * BSZ + bat) * MDIM) + m) * FDIM + f;
        g_hi[o] = h;
        g_lo[o] = __float2bfloat16(r);
    }
}

// ---------------- mma.sync helper (portable HMMA, sm_80+) ----------------
__device__ __forceinline__ void mma16816(float* c, const uint32_t* a, const uint32_t* b)
{
    asm volatile(
        "mma.sync.aligned.m16n8k16.row.col.f32.bf16.bf16.f32 "
        "{%0,%1,%2,%3}, {%4,%5,%6,%7}, {%8,%9}, {%0,%1,%2,%3};"
        : "+f"(c[0]), "+f"(c[1]), "+f"(c[2]), "+f"(c[3])
        : "r"(a[0]), "r"(a[1]), "r"(a[2]), "r"(a[3]), "r"(b[0]), "r"(b[1]));
}

// ---------------- kernel 2: pair GEMM (HMMA bf16 hi/lo split) + hist ----------------
// 256 threads = 8 warps (2 x 4). Warp tile 64x32. Each warp: 4 m-tiles x 4 n-tiles
// of m16n8k16, 3 products per k-step, acc fp32 in registers.
__global__ __launch_bounds__(256, 2)
void pair_hist_mma_kernel(float* __restrict__ out)
{
    const int a = blockIdx.x;
    const int b = blockIdx.y;
    if (b < a) return;
    const int z = blockIdx.z;

    extern __shared__ char dsm[];
    char* sAhi = dsm;
    char* sAlo = dsm + TBYTES;
    char* sBhi = dsm + 2 * TBYTES;
    char* sBlo = dsm + 3 * TBYTES;

    __shared__ float wmn[8], wmx[8];
    __shared__ float s_mn, s_sc;
    __shared__ unsigned int bins[8];

    const int tid  = threadIdx.x;
    const int wid  = tid >> 5;
    const int lane = tid & 31;
    const int wm   = wid & 1;          // 2 warp-rows (64 m each)
    const int wn   = wid >> 1;         // 4 warp-cols (32 n each)

    if (tid < 8) bins[tid] = 0u;

    // gmem bases (uint4 = 8 bf16); row stride = 256 bf16 = 32 uint4
    const uint4* gAhi = (const uint4*)g_hi + (size_t)(z * BSZ + a) * MDIM * 32;
    const uint4* gAlo = (const uint4*)g_lo + (size_t)(z * BSZ + a) * MDIM * 32;
    const uint4* gBhi = (const uint4*)g_hi + (size_t)(z * BSZ + b) * MDIM * 32;
    const uint4* gBlo = (const uint4*)g_lo + (size_t)(z * BSZ + b) * MDIM * 32;

    float acc[4][4][4];
#pragma unroll
    for (int i = 0; i < 4; i++)
#pragma unroll
        for (int j = 0; j < 4; j++)
#pragma unroll
            for (int q = 0; q < 4; q++) acc[i][j][q] = 0.0f;

    // fragment smem offsets (bytes), lane-dependent parts
    const int fr = lane >> 2;            // fragment row 0..7
    const int fk = (lane & 3) * 4;       // k-pair byte offset within k-step

    for (int c = 0; c < NCHUNK; c++) {
        // ---- cooperative load: 4 tiles x 1024 uint4 ----
#pragma unroll
        for (int i = 0; i < 4; i++) {
            int j = tid + i * 256;
            int m = j >> 3;
            int g = j & 7;
            int gidx = m * 32 + c * 8 + g;
            int so = m * (PITCH * 2) + g * 16;
            *(uint4*)(sAhi + so) = gAhi[gidx];
            *(uint4*)(sAlo + so) = gAlo[gidx];
            *(uint4*)(sBhi + so) = gBhi[gidx];
            *(uint4*)(sBlo + so) = gBlo[gidx];
        }
        __syncthreads();

        // ---- 4 k16-steps per chunk ----
#pragma unroll
        for (int ks = 0; ks < 4; ks++) {
            const int kb = ks * 32 + fk;     // byte offset of this lane's k-pair

            // B fragments for all 4 n-tiles (hi & lo)
            uint32_t Bh[4][2], Bl[4][2];
#pragma unroll
            for (int nt = 0; nt < 4; nt++) {
                int n = wn * 32 + nt * 8 + fr;
                int o = n * (PITCH * 2) + kb;
                Bh[nt][0] = *(const uint32_t*)(sBhi + o);
                Bh[nt][1] = *(const uint32_t*)(sBhi + o + 16);
                Bl[nt][0] = *(const uint32_t*)(sBlo + o);
                Bl[nt][1] = *(const uint32_t*)(sBlo + o + 16);
            }

#pragma unroll
            for (int mt = 0; mt < 4; mt++) {
                int m = wm * 64 + mt * 16 + fr;
                int o = m * (PITCH * 2) + kb;
                uint32_t Ah[4], Al[4];
                Ah[0] = *(const uint32_t*)(sAhi + o);
                Ah[1] = *(const uint32_t*)(sAhi + o + 8 * (PITCH * 2));
                Ah[2] = *(const uint32_t*)(sAhi + o + 16);
                Ah[3] = *(const uint32_t*)(sAhi + o + 8 * (PITCH * 2) + 16);
                Al[0] = *(const uint32_t*)(sAlo + o);
                Al[1] = *(const uint32_t*)(sAlo + o + 8 * (PITCH * 2));
                Al[2] = *(const uint32_t*)(sAlo + o + 16);
                Al[3] = *(const uint32_t*)(sAlo + o + 8 * (PITCH * 2) + 16);
#pragma unroll
                for (int nt = 0; nt < 4; nt++) {
                    mma16816(acc[mt][nt], Ah, Bh[nt]);   // hi*hi
                    mma16816(acc[mt][nt], Ah, Bl[nt]);   // hi*lo
                    mma16816(acc[mt][nt], Al, Bh[nt]);   // lo*hi
                }
            }
        }
        __syncthreads();
    }

    // ---- min/max over the 128x128 tile (values in registers) ----
    float mn = 3.4e38f, mx = -3.4e38f;
#pragma unroll
    for (int i = 0; i < 4; i++)
#pragma unroll
        for (int j = 0; j < 4; j++)
#pragma unroll
            for (int q = 0; q < 4; q++) {
                float v = acc[i][j][q];
                mn = fminf(mn, v);
                mx = fmaxf(mx, v);
            }
#pragma unroll
    for (int o = 16; o > 0; o >>= 1) {
        mn = fminf(mn, __shfl_xor_sync(0xffffffffu, mn, o));
        mx = fmaxf(mx, __shfl_xor_sync(0xffffffffu, mx, o));
    }
    if (lane == 0) { wmn[wid] = mn; wmx[wid] = mx; }
    __syncthreads();
    if (tid == 0) {
        float m0 = wmn[0], M0 = wmx[0];
#pragma unroll
        for (int w = 1; w < 8; w++) {
            m0 = fminf(m0, wmn[w]);
            M0 = fmaxf(M0, wmx[w]);
        }
        float den = (M0 > m0) ? (M0 - m0) : 1.0f;
        s_mn = m0;
        s_sc = 8.0f / den;
    }
    __syncthreads();

    // ---- binning into byte-packed counters (64 values/thread, max 64/bin) ----
    const float mnv = s_mn, sc = s_sc;
    unsigned int c0 = 0, c1 = 0;
#pragma unroll
    for (int i = 0; i < 4; i++)
#pragma unroll
        for (int j = 0; j < 4; j++)
#pragma unroll
            for (int q = 0; q < 4; q++) {
                float t = (acc[i][j][q] - mnv) * sc;
                int idx = (int)floorf(t);
                idx = idx < 0 ? 0 : (idx > 7 ? 7 : idx);
                unsigned int inc = 1u << ((idx & 3) * 8);
                if (idx < 4) c0 += inc; else c1 += inc;
            }
#pragma unroll
    for (int bbin = 0; bbin < 8; bbin++) {
        unsigned int v = (bbin < 4) ? ((c0 >> (bbin * 8)) & 0xFFu)
                                    : ((c1 >> ((bbin - 4) * 8)) & 0xFFu);
#pragma unroll
        for (int o = 16; o > 0; o >>= 1)
            v += __shfl_xor_sync(0xffffffffu, v, o);
        if (lane == 0) atomicAdd(&bins[bbin], v);
    }
    __syncthreads();

    // ---- L2 normalize and write both (a,b) and (b,a) rows ----
    if (tid == 0) {
        float h[8], ss = 0.0f;
#pragma unroll
        for (int k = 0; k < 8; k++) { h[k] = (float)bins[k]; ss += h[k] * h[k]; }
        float nrm = fmaxf(sqrtf(ss), 1e-12f);
        const int row1 = (a * BSZ + b) * 16 + z * 8;
        const int row2 = (b * BSZ + a) * 16 + z * 8;
#pragma unroll
        for (int k = 0; k < 8; k++) {
            float v = h[k] / nrm;
            out[row1 + k] = v;
            out[row2 + k] = v;
        }
    }
}

// ---------------- launch ----------------
extern "C" void kernel_launch(void* const* d_in, const int* in_sizes, int n_in,
                              void* d_out, int out_size)
{
    const float* m1 = (const float*)d_in[0];
    const float* m2 = (const float*)d_in[1];
    float* out = (float*)d_out;

    convert_kernel<<<dim3(MDIM / 32, FDIM / 32, 2 * BSZ), dim3(32, 8)>>>(m1, m2);

    cudaFuncSetAttribute(pair_hist_mma_kernel,
                         cudaFuncAttributeMaxDynamicSharedMemorySize, SMEM_DYN);
    pair_hist_mma_kernel<<<dim3(BSZ, BSZ, 2), 256, SMEM_DYN>>>(out);
}

// round 5
// speedup vs baseline: 2.0105x; 1.0030x over previous
#include <cuda_runtime.h>
#include <cuda_bf16.h>
#include <math.h>
#include <stdint.h>

// ---------------- problem constants ----------------
#define BSZ   64
#define FDIM  256
#define MDIM  128
#define KC    64                   // K elements per chunk
#define NCHUNK (FDIM / KC)         // 4
#define PITCH 72                   // bf16 elems per smem row (144 B, 16B-aligned, LDS conflict-free)
#define TBYTES (MDIM * PITCH * 2)  // 18432 B per tile
#define SMEM_DYN (4 * TBYTES)      // Ahi, Alo, Bhi, Blo

// bf16 hi/lo scratch, K-major: [z][batch][m][f]  (8 MB each)
__device__ __nv_bfloat16 g_hi[2u * BSZ * MDIM * FDIM];
__device__ __nv_bfloat16 g_lo[2u * BSZ * MDIM * FDIM];

// ---------------- kernel 1: fp32 -> (hi, lo) bf16 with F<->M transpose ----------------
// in : [bs, F=256, M=128] fp32 ;  out: [z, bs, M=128, F=256] bf16 (K-major)
__global__ void convert_kernel(const float* __restrict__ m1, const float* __restrict__ m2)
{
    __shared__ float tile[32][33];
    const int z = blockIdx.z >> 6;
    const int bat = blockIdx.z & 63;
    const float* __restrict__ src = z ? m2 : m1;
    const int m0 = blockIdx.x * 32;
    const int f0 = blockIdx.y * 32;
    const int tx = threadIdx.x, ty = threadIdx.y;

#pragma unroll
    for (int i = 0; i < 4; i++) {
        int f = f0 + ty + i * 8;
        tile[ty + i * 8][tx] = src[((size_t)bat * FDIM + f) * MDIM + m0 + tx];
    }
    __syncthreads();
#pragma unroll
    for (int i = 0; i < 4; i++) {
        int m = m0 + ty + i * 8;
        int f = f0 + tx;
        float x = tile[tx][ty + i * 8];
        __nv_bfloat16 h = __float2bfloat16(x);
        float r = x - __bfloat162float(h);
        size_t o = (((size_t)(z * BSZ + bat) * MDIM) + m) * FDIM + f;
        g_hi[o] = h;
        g_lo[o] = __float2bfloat16(r);
    }
}

// ---------------- mma.sync helper (portable HMMA, sm_80+) ----------------
__device__ __forceinline__ void mma16816(float* c, const uint32_t* a, const uint32_t* b)
{
    asm volatile(
        "mma.sync.aligned.m16n8k16.row.col.f32.bf16.bf16.f32 "
        "{%0,%1,%2,%3}, {%4,%5,%6,%7}, {%8,%9}, {%0,%1,%2,%3};"
        : "+f"(c[0]), "+f"(c[1]), "+f"(c[2]), "+f"(c[3])
        : "r"(a[0]), "r"(a[1]), "r"(a[2]), "r"(a[3]), "r"(b[0]), "r"(b[1]));
}

// ---------------- kernel 2: pair GEMM (HMMA bf16 hi/lo split) + hist ----------------
// 256 threads = 8 warps (2 x 4). Warp tile 64x32. Each warp: 4 m-tiles x 4 n-tiles
// of m16n8k16, 3 products per k-step, acc fp32 in registers.
__global__ __launch_bounds__(256, 2)
void pair_hist_mma_kernel(float* __restrict__ out)
{
    const int a = blockIdx.x;
    const int b = blockIdx.y;
    if (b < a) return;
    const int z = blockIdx.z;

    extern __shared__ char dsm[];
    char* sAhi = dsm;
    char* sAlo = dsm + TBYTES;
    char* sBhi = dsm + 2 * TBYTES;
    char* sBlo = dsm + 3 * TBYTES;

    __shared__ float wmn[8], wmx[8];
    __shared__ float s_mn, s_sc;
    __shared__ unsigned int bins[8];

    const int tid  = threadIdx.x;
    const int wid  = tid >> 5;
    const int lane = tid & 31;
    const int wm   = wid & 1;          // 2 warp-rows (64 m each)
    const int wn   = wid >> 1;         // 4 warp-cols (32 n each)

    if (tid < 8) bins[tid] = 0u;

    // gmem bases (uint4 = 8 bf16); row stride = 256 bf16 = 32 uint4
    const uint4* gAhi = (const uint4*)g_hi + (size_t)(z * BSZ + a) * MDIM * 32;
    const uint4* gAlo = (const uint4*)g_lo + (size_t)(z * BSZ + a) * MDIM * 32;
    const uint4* gBhi = (const uint4*)g_hi + (size_t)(z * BSZ + b) * MDIM * 32;
    const uint4* gBlo = (const uint4*)g_lo + (size_t)(z * BSZ + b) * MDIM * 32;

    float acc[4][4][4];
#pragma unroll
    for (int i = 0; i < 4; i++)
#pragma unroll
        for (int j = 0; j < 4; j++)
#pragma unroll
            for (int q = 0; q < 4; q++) acc[i][j][q] = 0.0f;

    // fragment smem offsets (bytes), lane-dependent parts
    const int fr = lane >> 2;            // fragment row 0..7
    const int fk = (lane & 3) * 4;       // k-pair byte offset within k-step

    for (int c = 0; c < NCHUNK; c++) {
        // ---- cooperative load: 4 tiles x 1024 uint4 ----
#pragma unroll
        for (int i = 0; i < 4; i++) {
            int j = tid + i * 256;
            int m = j >> 3;
            int g = j & 7;
            int gidx = m * 32 + c * 8 + g;
            int so = m * (PITCH * 2) + g * 16;
            *(uint4*)(sAhi + so) = gAhi[gidx];
            *(uint4*)(sAlo + so) = gAlo[gidx];
            *(uint4*)(sBhi + so) = gBhi[gidx];
            *(uint4*)(sBlo + so) = gBlo[gidx];
        }
        __syncthreads();

        // ---- 4 k16-steps per chunk ----
#pragma unroll
        for (int ks = 0; ks < 4; ks++) {
            const int kb = ks * 32 + fk;     // byte offset of this lane's k-pair

            // B fragments for all 4 n-tiles (hi & lo)
            uint32_t Bh[4][2], Bl[4][2];
#pragma unroll
            for (int nt = 0; nt < 4; nt++) {
                int n = wn * 32 + nt * 8 + fr;
                int o = n * (PITCH * 2) + kb;
                Bh[nt][0] = *(const uint32_t*)(sBhi + o);
                Bh[nt][1] = *(const uint32_t*)(sBhi + o + 16);
                Bl[nt][0] = *(const uint32_t*)(sBlo + o);
                Bl[nt][1] = *(const uint32_t*)(sBlo + o + 16);
            }

#pragma unroll
            for (int mt = 0; mt < 4; mt++) {
                int m = wm * 64 + mt * 16 + fr;
                int o = m * (PITCH * 2) + kb;
                uint32_t Ah[4], Al[4];
                Ah[0] = *(const uint32_t*)(sAhi + o);
                Ah[1] = *(const uint32_t*)(sAhi + o + 8 * (PITCH * 2));
                Ah[2] = *(const uint32_t*)(sAhi + o + 16);
                Ah[3] = *(const uint32_t*)(sAhi + o + 8 * (PITCH * 2) + 16);
                Al[0] = *(const uint32_t*)(sAlo + o);
                Al[1] = *(const uint32_t*)(sAlo + o + 8 * (PITCH * 2));
                Al[2] = *(const uint32_t*)(sAlo + o + 16);
                Al[3] = *(const uint32_t*)(sAlo + o + 8 * (PITCH * 2) + 16);
#pragma unroll
                for (int nt = 0; nt < 4; nt++) {
                    mma16816(acc[mt][nt], Ah, Bh[nt]);   // hi*hi
                    mma16816(acc[mt][nt], Ah, Bl[nt]);   // hi*lo
                    mma16816(acc[mt][nt], Al, Bh[nt]);   // lo*hi
                }
            }
        }
        __syncthreads();
    }

    // ---- min/max over the 128x128 tile (values in registers) ----
    float mn = 3.4e38f, mx = -3.4e38f;
#pragma unroll
    for (int i = 0; i < 4; i++)
#pragma unroll
        for (int j = 0; j < 4; j++)
#pragma unroll
            for (int q = 0; q < 4; q++) {
                float v = acc[i][j][q];
                mn = fminf(mn, v);
                mx = fmaxf(mx, v);
            }
#pragma unroll
    for (int o = 16; o > 0; o >>= 1) {
        mn = fminf(mn, __shfl_xor_sync(0xffffffffu, mn, o));
        mx = fmaxf(mx, __shfl_xor_sync(0xffffffffu, mx, o));
    }
    if (lane == 0) { wmn[wid] = mn; wmx[wid] = mx; }
    __syncthreads();
    if (tid == 0) {
        float m0 = wmn[0], M0 = wmx[0];
#pragma unroll
        for (int w = 1; w < 8; w++) {
            m0 = fminf(m0, wmn[w]);
            M0 = fmaxf(M0, wmx[w]);
        }
        float den = (M0 > m0) ? (M0 - m0) : 1.0f;
        s_mn = m0;
        s_sc = 8.0f / den;
    }
    __syncthreads();

    // ---- binning into byte-packed counters (64 values/thread, max 64/bin) ----
    const float mnv = s_mn, sc = s_sc;
    unsigned int c0 = 0, c1 = 0;
#pragma unroll
    for (int i = 0; i < 4; i++)
#pragma unroll
        for (int j = 0; j < 4; j++)
#pragma unroll
            for (int q = 0; q < 4; q++) {
                float t = (acc[i][j][q] - mnv) * sc;
                int idx = (int)floorf(t);
                idx = idx < 0 ? 0 : (idx > 7 ? 7 : idx);
                unsigned int inc = 1u << ((idx & 3) * 8);
                if (idx < 4) c0 += inc; else c1 += inc;
            }
#pragma unroll
    for (int bbin = 0; bbin < 8; bbin++) {
        unsigned int v = (bbin < 4) ? ((c0 >> (bbin * 8)) & 0xFFu)
                                    : ((c1 >> ((bbin - 4) * 8)) & 0xFFu);
#pragma unroll
        for (int o = 16; o > 0; o >>= 1)
            v += __shfl_xor_sync(0xffffffffu, v, o);
        if (lane == 0) atomicAdd(&bins[bbin], v);
    }
    __syncthreads();

    // ---- L2 normalize and write both (a,b) and (b,a) rows ----
    if (tid == 0) {
        float h[8], ss = 0.0f;
#pragma unroll
        for (int k = 0; k < 8; k++) { h[k] = (float)bins[k]; ss += h[k] * h[k]; }
        float nrm = fmaxf(sqrtf(ss), 1e-12f);
        const int row1 = (a * BSZ + b) * 16 + z * 8;
        const int row2 = (b * BSZ + a) * 16 + z * 8;
#pragma unroll
        for (int k = 0; k < 8; k++) {
            float v = h[k] / nrm;
            out[row1 + k] = v;
            out[row2 + k] = v;
        }
    }
}

// ---------------- launch ----------------
extern "C" void kernel_launch(void* const* d_in, const int* in_sizes, int n_in,
                              void* d_out, int out_size)
{
    const float* m1 = (const float*)d_in[0];
    const float* m2 = (const float*)d_in[1];
    float* out = (float*)d_out;

    convert_kernel<<<dim3(MDIM / 32, FDIM / 32, 2 * BSZ), dim3(32, 8)>>>(m1, m2);

    cudaFuncSetAttribute(pair_hist_mma_kernel,
                         cudaFuncAttributeMaxDynamicSharedMemorySize, SMEM_DYN);
    pair_hist_mma_kernel<<<dim3(BSZ, BSZ, 2), 256, SMEM_DYN>>>(out);
}